// round 10
// baseline (speedup 1.0000x reference)
#include <cuda_runtime.h>
#include <cuda_bf16.h>
#include <math.h>

#define Bsz   16
#define CH    32
#define DCH   3
#define S     128
#define HH    255
#define WW    255
#define WP    256
#define NPIX  (HH*WW)
#define M12   12
#define KX24  24
#define ROWS  (Bsz*CH*HH)          // 130560
#define BN_EPS 1e-5f

typedef unsigned long long ull;

// ---------------- packed f32x2 helpers ----------------
__device__ __forceinline__ ull pack2(float lo, float hi) {
    ull r; asm("mov.b64 %0, {%1,%2};" : "=l"(r) : "f"(lo), "f"(hi)); return r;
}
__device__ __forceinline__ void unpack2(ull v, float& lo, float& hi) {
    asm("mov.b64 {%0,%1}, %2;" : "=f"(lo), "=f"(hi) : "l"(v));
}
__device__ __forceinline__ ull ffma2(ull a, ull b, ull c) {
    ull d; asm("fma.rn.f32x2 %0, %1, %2, %3;" : "=l"(d) : "l"(a), "l"(b), "l"(c)); return d;
}
__device__ __forceinline__ ull fadd2(ull a, ull b) {
    ull d; asm("add.rn.f32x2 %0, %1, %2;" : "=l"(d) : "l"(a), "l"(b)); return d;
}

// ---------------- scratch ----------------
__device__ __align__(16) float  g_h[Bsz*CH*HH*WP];
__device__ __align__(16) float  g_t[Bsz*CH*HH*WP];
__device__ __align__(16) float2 g_Y [ROWS*M12];
__device__ __align__(16) float2 g_Z [Bsz*CH*KX24*M12];
__device__ __align__(16) float2 g_Zm[Bsz*CH*KX24*M12];
__device__ __align__(16) float2 g_Yi[ROWS*M12];
__device__ __align__(16) float2 g_ET[13*256];   // e^{-i 2pi k t /255}, k=0..12; t=255 -> (0,0)
__device__ float  g_sum[CH], g_sumsq[CH];
__device__ float  g_scale[CH], g_shift[CH];

// ---------------- init ----------------
__global__ void k_init() {
    int t = blockIdx.x * blockDim.x + threadIdx.x;
    if (t < 13*256) {
        int k = t >> 8, w = t & 255;
        float2 e = make_float2(0.f, 0.f);
        if (w < 255) {
            int m = (k * w) % 255;
            float a = 2.0f * (float)m / 255.0f;
            e = make_float2(cospif(a), -sinpif(a));
        }
        g_ET[t] = e;
    }
    if (t < CH) { g_sum[t] = 0.f; g_sumsq[t] = 0.f; }
}

// ---------------- K0: mirror + fc0 ----------------
__global__ void k0_fc0(const float* __restrict__ x,
                       const float* __restrict__ fc0_w,
                       const float* __restrict__ fc0_b) {
    __shared__ float sW[DCH*CH];
    __shared__ float sB[CH];
    if (threadIdx.x < DCH*CH) sW[threadIdx.x] = fc0_w[threadIdx.x];
    if (threadIdx.x < CH)     sB[threadIdx.x] = fc0_b[threadIdx.x];
    __syncthreads();

    int g = blockIdx.x * blockDim.x + threadIdx.x;
    if (g >= Bsz * NPIX) return;
    int b = g / NPIX, p = g % NPIX;
    int i = p / WW, j = p % WW;
    int sr = (i < S-1) ? (S-1 - i) : (i - (S-1));
    int sc = (j < S-1) ? (S-1 - j) : (j - (S-1));
    float sign = ((i < S-1) == (j < S-1)) ? 1.0f : -1.0f;

    float v[DCH];
#pragma unroll
    for (int c = 0; c < DCH; c++)
        v[c] = sign * x[((b*DCH + c)*S + sr)*S + sc];

#pragma unroll
    for (int d = 0; d < CH; d++) {
        float acc = sB[d];
#pragma unroll
        for (int c = 0; c < DCH; c++) acc += v[c] * sW[c*CH + d];
        g_h[((size_t)(b*CH + d)*HH + i)*WP + j] = acc;
    }
}

// ---------------- K1: forward DFT along w. 192 thr: 32 rows x 6 k-slots (kk, kk+6) ----------------
// Output Y[r][k] written directly as packed (Yr,Yi) -- no reduction.
__global__ __launch_bounds__(192) void k1_fwd_w(int prev_bn) {
    extern __shared__ float sm1[];
    float*  sX  = sm1;                       // 32 rows x 260
    float2* sE2 = (float2*)(sm1 + 32*260);   // 12 rows x 258 (padded)

    int tid = threadIdx.x;
    // E table (rows 0..11), re-strided to 258
    for (int t = tid; t < 12*256; t += 192) {
        int k = t >> 8, w = t & 255;
        sE2[k*258 + w] = g_ET[t];
    }
    // load 32 rows, BN+relu folded
    const float* src = prev_bn ? g_t : g_h;
    int r0 = blockIdx.x * 32;
    for (int t = tid; t < 32*64; t += 192) {
        int rl = t >> 6, seg = t & 63;
        int rg = r0 + rl;
        float4 v = *(const float4*)&src[(size_t)rg*WP + seg*4];
        if (prev_bn) {
            int c = (rg / HH) & (CH-1);
            float scl = g_scale[c], shf = g_shift[c];
            v.x = fmaxf(v.x*scl + shf, 0.f);
            v.y = fmaxf(v.y*scl + shf, 0.f);
            v.z = fmaxf(v.z*scl + shf, 0.f);
            v.w = fmaxf(v.w*scl + shf, 0.f);
        }
        if (seg == 63) v.w = 0.f;            // pad column
        *(float4*)&sX[rl*260 + seg*4] = v;
    }
    __syncthreads();

    int rid = tid / 6, kk = tid % 6;
    int kkA = kk, kkB = kk + 6;
    ull accA1 = 0, accA2 = 0, accB1 = 0, accB2 = 0;
    const float* xr = sX + rid*260;

#pragma unroll 4
    for (int wp = 0; wp < 128; wp++) {
        int w = wp*2;
        float2 x2 = *(const float2*)&xr[w];
        ulonglong2 ea = *(const ulonglong2*)&sE2[kkA*258 + w];
        ulonglong2 eb = *(const ulonglong2*)&sE2[kkB*258 + w];
        ull x00 = pack2(x2.x, x2.x);
        ull x11 = pack2(x2.y, x2.y);
        accA1 = ffma2(ea.x, x00, accA1);
        accA2 = ffma2(ea.y, x11, accA2);
        accB1 = ffma2(eb.x, x00, accB1);
        accB2 = ffma2(eb.y, x11, accB2);
    }
    int rg = r0 + rid;
    ((ull*)g_Y)[(size_t)rg*M12 + kkA] = fadd2(accA1, accA2);
    ((ull*)g_Y)[(size_t)rg*M12 + kkB] = fadd2(accB1, accB2);
}

// ---------------- K2: forward DFT along h, pre-conjugated 24-row E table, 2-way ILP ----------------
__global__ __launch_bounds__(288) void k2_fwd_h() {
    extern __shared__ float sm2[];
    float2* sY   = (float2*)sm2;         // 3060
    float2* sE24 = sY + HH*M12;          // 24*256

    int bc = blockIdx.x;
    for (int t = threadIdx.x; t < HH*M12; t += 288)
        sY[t] = g_Y[(size_t)bc*HH*M12 + t];
    for (int t = threadIdx.x; t < 24*256; t += 288) {
        int kxi = t >> 8, h = t & 255;
        int kr = (kxi < M12) ? kxi : (24 - kxi);
        float2 e = g_ET[kr*256 + h];
        if (kxi >= M12) e.y = -e.y;
        sE24[t] = e;
    }
    __syncthreads();

    int t = threadIdx.x;                 // 288 = 24*12
    int kxi = t / M12, ky = t % M12;
    const float2* Er = sE24 + kxi*256;

    float zr0=0.f, zi0=0.f, zr1=0.f, zi1=0.f;
#pragma unroll 2
    for (int h = 0; h < 254; h += 2) {
        float2 y0 = sY[h*M12 + ky];
        float2 e0 = Er[h];
        float2 y1 = sY[(h+1)*M12 + ky];
        float2 e1 = Er[h+1];
        zr0 += y0.x*e0.x - y0.y*e0.y;
        zi0 += y0.x*e0.y + y0.y*e0.x;
        zr1 += y1.x*e1.x - y1.y*e1.y;
        zi1 += y1.x*e1.y + y1.y*e1.x;
    }
    {   // tail h = 254
        float2 y = sY[254*M12 + ky];
        float2 e = Er[254];
        zr0 += y.x*e.x - y.y*e.y;
        zi0 += y.x*e.y + y.y*e.x;
    }
    g_Z[(size_t)bc*(KX24*M12) + t] = make_float2(zr0+zr1, zi0+zi1);
}

// ---------------- K3: mode mix ----------------
__global__ void k3_mix(const float* __restrict__ spec_w, int layer) {
    __shared__ float2 sZ[Bsz*CH];
    int f = blockIdx.x;
    int kxi = f / M12, ky = f % M12;
    int region = (kxi < M12) ? 0 : 1;
    int xx = (kxi < M12) ? kxi : (kxi - M12);

    int tb = threadIdx.x / CH;
    int o  = threadIdx.x % CH;
    sZ[tb*CH + o] = g_Z[((size_t)(tb*CH + o))*(KX24*M12) + f];
    __syncthreads();

    const float* Wb = spec_w + (size_t)(layer*2 + region)*CH*CH*M12*M12*2
                             + (size_t)(xx*M12 + ky)*2;
    float orr = 0.f, oii = 0.f;
#pragma unroll 4
    for (int i = 0; i < CH; i++) {
        float2 z = sZ[tb*CH + i];
        const float* wp = Wb + (size_t)(i*CH + o)*(M12*M12*2);
        float wr = wp[0], wi = wp[1];
        orr += z.x*wr - z.y*wi;
        oii += z.x*wi + z.y*wr;
    }
    g_Zm[((size_t)(tb*CH + o))*(KX24*M12) + f] = make_float2(orr, oii);
}

// ---------------- K4: inverse DFT along h; 240 thr, Z in registers, 2-way ILP ----------------
__global__ __launch_bounds__(240) void k4_inv_h() {
    extern __shared__ float sm4[];
    float2* sZ   = (float2*)sm4;       // 288
    float2* sE24 = sZ + KX24*M12;      // 24*256

    int bc = blockIdx.x;
    for (int t = threadIdx.x; t < KX24*M12; t += 240)
        sZ[t] = g_Zm[(size_t)bc*(KX24*M12) + t];
    for (int t = threadIdx.x; t < 24*256; t += 240) {
        int kxi = t >> 8, h = t & 255;
        int kr = (kxi < M12) ? kxi : (24 - kxi);
        float2 e = g_ET[kr*256 + h];
        if (kxi >= M12) e.y = -e.y;
        sE24[t] = e;
    }
    __syncthreads();

    int ky = threadIdx.x % M12, hg = threadIdx.x / M12;   // hg 0..19
    float2 z[KX24];
#pragma unroll
    for (int kxi = 0; kxi < KX24; kxi++) z[kxi] = sZ[kxi*M12 + ky];

    for (int hh = hg; hh < HH; hh += 20) {
        float yr0=0.f, yi0=0.f, yr1=0.f, yi1=0.f;
#pragma unroll
        for (int kxi = 0; kxi < KX24; kxi += 2) {
            float2 e0 = sE24[kxi*256 + hh];
            float2 e1 = sE24[(kxi+1)*256 + hh];
            // Yi += z * conj(E)
            yr0 += z[kxi].x*e0.x + z[kxi].y*e0.y;
            yi0 += z[kxi].y*e0.x - z[kxi].x*e0.y;
            yr1 += z[kxi+1].x*e1.x + z[kxi+1].y*e1.y;
            yi1 += z[kxi+1].y*e1.x - z[kxi+1].x*e1.y;
        }
        g_Yi[((size_t)bc*HH + hh)*M12 + ky] = make_float2(yr0+yr1, yi0+yi1);
    }
}

// ---------------- K5: fused inverse-w + 1x1 conv + bias + BN stats (f32x2) ----------------
__global__ __launch_bounds__(256, 2) void k5_invw_conv(const float* __restrict__ conv_w,
                                                       const float* __restrict__ conv_b,
                                                       int layer, int prev_bn) {
    extern __shared__ float sm5[];
    float*  sH  = sm5;                              // 32*256 = 8192
    float2* sE  = (float2*)(sm5 + 8192);            // 12*256 float2
    float2* sQ  = (float2*)(sm5 + 8192 + 6144);     // 32*12 float2
    float*  sCw = sm5 + 8192 + 6144 + 768;          // 1024
    float*  sCb = sCw + 1024;
    float*  ssum = sCb + 32;
    float*  ssq  = ssum + 32;
    float*  sScl = ssq + 32;
    float*  sShf = sScl + 32;

    int b = blockIdx.x / HH, hh = blockIdx.x % HH;
    int tid = threadIdx.x;

    // E rows 0..11 contiguous in g_ET: plain float4 copy
    for (int t = tid; t < 1536; t += 256)
        *(float4*)((float*)sE + t*4) = *(const float4*)((const float*)g_ET + t*4);
    for (int t = tid; t < CH*CH; t += 256) sCw[t] = conv_w[layer*CH*CH + t];
    if (tid < CH) {
        sCb[tid]  = conv_b[layer*CH + tid];
        ssum[tid] = 0.f; ssq[tid] = 0.f;
        sScl[tid] = prev_bn ? g_scale[tid] : 1.f;
        sShf[tid] = prev_bn ? g_shift[tid] : 0.f;
    }
    __syncthreads();

    const float* src = prev_bn ? g_t : g_h;
    for (int t = tid; t < 32*64; t += 256) {
        int c = t >> 6, seg = t & 63;
        float4 v = *(const float4*)&src[((size_t)(b*CH + c)*HH + hh)*WP + seg*4];
        if (prev_bn) {
            float scl = sScl[c], shf = sShf[c];
            v.x = fmaxf(v.x*scl + shf, 0.f);
            v.y = fmaxf(v.y*scl + shf, 0.f);
            v.z = fmaxf(v.z*scl + shf, 0.f);
            v.w = fmaxf(v.w*scl + shf, 0.f);
        }
        if (seg == 63) v.w = 0.f;
        *(float4*)&sH[c*256 + seg*4] = v;
    }
    const float dsc = 1.0f / 65025.0f;
    for (int t = tid; t < CH*M12; t += 256) {
        int c = t / M12, ky = t % M12;
        float2 y = g_Yi[((size_t)(b*CH + c)*HH + hh)*M12 + ky];
        float f = (ky == 0) ? dsc : 2.0f*dsc;
        sQ[t] = make_float2(y.x*f, y.y*f);
    }
    __syncthreads();

    int o = tid >> 3, wsub = tid & 7;
    ull w2[CH];
#pragma unroll
    for (int c = 0; c < CH; c++) { float wc = sCw[o*CH + c]; w2[c] = pack2(wc, wc); }
    float cb = sCb[o];
    const ull* q2 = (const ull*)(sQ + o*M12);
    ull lsum2 = 0, lsq2 = 0;
    float* orow = g_t + ((size_t)(b*CH + o)*HH + hh)*WP;

#pragma unroll
    for (int it = 0; it < 8; it++) {
        int wb = it*32 + wsub*4;
        ull s0=0, s1=0, s2=0, s3=0;
#pragma unroll
        for (int k = 0; k < M12; k++) {
            ulonglong2 eA = *(const ulonglong2*)&sE[k*256 + wb];
            ulonglong2 eB = *(const ulonglong2*)&sE[k*256 + wb + 2];
            ull q = q2[k];
            s0 = ffma2(eA.x, q, s0);
            s1 = ffma2(eA.y, q, s1);
            s2 = ffma2(eB.x, q, s2);
            s3 = ffma2(eB.y, q, s3);
        }
        ull c01 = pack2(cb, cb), c23 = pack2(cb, cb);
#pragma unroll
        for (int c = 0; c < CH; c++) {
            ulonglong2 h2 = *(const ulonglong2*)&sH[c*256 + wb];
            c01 = ffma2(h2.x, w2[c], c01);
            c23 = ffma2(h2.y, w2[c], c23);
        }
        float a0,b0,a1,b1,a2,b2,a3,b3;
        unpack2(s0,a0,b0); unpack2(s1,a1,b1); unpack2(s2,a2,b2); unpack2(s3,a3,b3);
        ull r01 = fadd2(c01, pack2(a0+b0, a1+b1));
        ull r23 = fadd2(c23, pack2(a2+b2, a3+b3));
        if (wb == 252) { float lo, hi; unpack2(r23, lo, hi); r23 = pack2(lo, 0.f); }
        *(ulonglong2*)&orow[wb] = make_ulonglong2(r01, r23);
        lsum2 = fadd2(lsum2, fadd2(r01, r23));
        lsq2 = ffma2(r01, r01, lsq2);
        lsq2 = ffma2(r23, r23, lsq2);
    }
    float sa, sb;
    unpack2(lsum2, sa, sb); float lsum = sa + sb;
    unpack2(lsq2,  sa, sb); float lsq  = sa + sb;
    atomicAdd(&ssum[o], lsum);
    atomicAdd(&ssq[o],  lsq);
    __syncthreads();
    if (tid < CH) {
        atomicAdd(&g_sum[tid],   ssum[tid]);
        atomicAdd(&g_sumsq[tid], ssq[tid]);
    }
}

// ---------------- K6: finalize BN stats ----------------
__global__ void k6_bn(const float* __restrict__ bn_g, const float* __restrict__ bn_b,
                      int layer) {
    int c = threadIdx.x;
    if (c < CH) {
        const float N = (float)Bsz * (float)NPIX;
        float mean = g_sum[c] / N;
        float var  = g_sumsq[c] / N - mean*mean;
        float inv  = rsqrtf(var + BN_EPS);
        float gg = bn_g[layer*CH + c], bb = bn_b[layer*CH + c];
        g_scale[c] = gg * inv;
        g_shift[c] = bb - gg * inv * mean;
        g_sum[c] = 0.f; g_sumsq[c] = 0.f;
    }
}

// ---------------- K8: head ----------------
__global__ __launch_bounds__(128) void k8_head(const float* __restrict__ fc1_w,
                                               const float* __restrict__ fc1_b,
                                               const float* __restrict__ fc2_w,
                                               const float* __restrict__ fc2_b,
                                               float* __restrict__ out) {
    __shared__ float W1T[128][36];
    __shared__ float b1[128];
    __shared__ float W2[128];
    __shared__ float sc[CH], sh[CH];

    for (int t = threadIdx.x; t < CH*128; t += 128) {
        int c = t >> 7, d = t & 127;
        W1T[d][c] = fc1_w[t];
    }
    b1[threadIdx.x] = fc1_b[threadIdx.x];
    W2[threadIdx.x] = fc2_w[threadIdx.x];
    if (threadIdx.x < CH) { sc[threadIdx.x] = g_scale[threadIdx.x]; sh[threadIdx.x] = g_shift[threadIdx.x]; }
    __syncthreads();

    int p = blockIdx.x * 128 + threadIdx.x;
    if (p >= Bsz*S*S) return;
    int b = p >> 14, q = p & 16383;
    int ii = q >> 7, jj = q & 127;
    int i = ii + (S-1), j = jj + (S-1);

    float in[CH];
#pragma unroll
    for (int c = 0; c < CH; c++)
        in[c] = g_t[((size_t)(b*CH + c)*HH + i)*WP + j] * sc[c] + sh[c];

    float acc = fc2_b[0];
#pragma unroll 2
    for (int d = 0; d < 128; d++) {
        float a = b1[d];
#pragma unroll
        for (int c4 = 0; c4 < CH; c4 += 4) {
            float4 w4 = *(const float4*)&W1T[d][c4];
            a += in[c4]*w4.x + in[c4+1]*w4.y + in[c4+2]*w4.z + in[c4+3]*w4.w;
        }
        a = fmaxf(a, 0.f);
        acc += a * W2[d];
    }
#pragma unroll
    for (int c3 = 0; c3 < DCH; c3++)
        out[((b*DCH + c3)*S + ii)*S + jj] = acc;
}

// ---------------- launch ----------------
extern "C" void kernel_launch(void* const* d_in, const int* in_sizes, int n_in,
                              void* d_out, int out_size) {
    const float* x      = (const float*)d_in[0];
    const float* fc0_w  = (const float*)d_in[1];
    const float* fc0_b  = (const float*)d_in[2];
    const float* spec_w = (const float*)d_in[3];
    const float* conv_w = (const float*)d_in[4];
    const float* conv_b = (const float*)d_in[5];
    const float* bn_g   = (const float*)d_in[6];
    const float* bn_b   = (const float*)d_in[7];
    const float* fc1_w  = (const float*)d_in[8];
    const float* fc1_b  = (const float*)d_in[9];
    const float* fc2_w  = (const float*)d_in[10];
    const float* fc2_b  = (const float*)d_in[11];
    float* out = (float*)d_out;

    const int K1_SMEM = (32*260)*4 + (12*258)*8;          // 58048
    const int K2_SMEM = (HH*M12)*8 + (24*256)*8;          // 73632
    const int K4_SMEM = (KX24*M12)*8 + (24*256)*8;        // 51456
    const int K5_SMEM = (8192 + 6144 + 768 + 1024 + 32*5) * 4;  // 65152

    cudaFuncSetAttribute(k1_fwd_w,    cudaFuncAttributeMaxDynamicSharedMemorySize, K1_SMEM);
    cudaFuncSetAttribute(k2_fwd_h,    cudaFuncAttributeMaxDynamicSharedMemorySize, K2_SMEM);
    cudaFuncSetAttribute(k4_inv_h,    cudaFuncAttributeMaxDynamicSharedMemorySize, K4_SMEM);
    cudaFuncSetAttribute(k5_invw_conv,cudaFuncAttributeMaxDynamicSharedMemorySize, K5_SMEM);

    k_init<<<13, 256>>>();
    k0_fc0<<<(Bsz*NPIX + 255)/256, 256>>>(x, fc0_w, fc0_b);

    for (int layer = 0; layer < 4; layer++) {
        int prev_bn = (layer > 0) ? 1 : 0;
        k1_fwd_w<<<ROWS/32, 192, K1_SMEM>>>(prev_bn);
        k2_fwd_h<<<Bsz*CH, 288, K2_SMEM>>>();
        k3_mix<<<KX24*M12, Bsz*CH>>>(spec_w, layer);
        k4_inv_h<<<Bsz*CH, 240, K4_SMEM>>>();
        k5_invw_conv<<<Bsz*HH, 256, K5_SMEM>>>(conv_w, conv_b, layer, prev_bn);
        k6_bn<<<1, 32>>>(bn_g, bn_b, layer);
    }
    k8_head<<<(Bsz*S*S + 127)/128, 128>>>(fc1_w, fc1_b, fc2_w, fc2_b, out);
}